// round 1
// baseline (speedup 1.0000x reference)
#include <cuda_runtime.h>
#include <math.h>

#define NM     1024
#define NA     32
#define ZD     64
#define HID    256
#define NT     10
#define NBOND  5
#define NEDGE  496
#define TOTA   32768
#define ATOM_OUT (TOTA*NT)   /* 327680 floats of atom_types, then edge_types */

// ---------------- device scratch (static, no allocation) ----------------
__device__ float g_Gpart[256*4096];   // per-block partial Gram
__device__ float g_spart[256*64];     // per-block partial colsum
__device__ float g_G[4096];           // Z^T Z  (64x64)
__device__ float g_s[64];             // colsum(Z)
__device__ float g_A[HID];            // folded BN scale  (rstd*gamma)
__device__ float g_B[HID];            // folded BN shift  ((b1-mean)*A + beta)
__device__ float g_Wf[NBOND*ZD*ZD];   // symmetrized bond matrix, [t*64+d][c]

// ---------------- K0: symmetrize bond matrix ----------------
__global__ void k_prep(const float* __restrict__ bm) {
    int idx = blockIdx.x*256 + threadIdx.x;
    if (idx < NBOND*ZD*ZD) {
        int t = idx >> 12;
        int d = (idx >> 6) & 63;
        int c = idx & 63;
        g_Wf[idx] = 0.5f*(bm[(t<<12) + (d<<6) + c] + bm[(t<<12) + (c<<6) + d]);
    }
}

// ---------------- K1: partial Gram + colsum (128 rows / block) ----------------
__global__ void k_stats(const float* __restrict__ z) {
    __shared__ float zs[128*68];          // padded stride 68
    int b = blockIdx.x, tid = threadIdx.x;
    const float* zp = z + b*(128*64);
    for (int idx = tid; idx < 128*64; idx += 256)
        zs[(idx>>6)*68 + (idx&63)] = zp[idx];
    __syncthreads();

    int i0 = (tid & 15) << 2;
    int j0 = (tid >> 4) << 2;
    float acc[16];
#pragma unroll
    for (int k = 0; k < 16; k++) acc[k] = 0.f;

    for (int r = 0; r < 128; r++) {
        float zi[4], zj[4];
#pragma unroll
        for (int x = 0; x < 4; x++) { zi[x] = zs[r*68 + i0 + x]; zj[x] = zs[r*68 + j0 + x]; }
#pragma unroll
        for (int x = 0; x < 4; x++)
#pragma unroll
            for (int y = 0; y < 4; y++)
                acc[x*4+y] += zi[x]*zj[y];
    }
    // coalesced partial store; index mapping undone in k_reduce
    float* gp = g_Gpart + b*4096;
#pragma unroll
    for (int k = 0; k < 16; k++) gp[tid*16 + k] = acc[k];

    if (tid < 64) {
        float s = 0.f;
        for (int r = 0; r < 128; r++) s += zs[r*68 + tid];
        g_spart[b*64 + tid] = s;
    }
}

// ---------------- K1b: deterministic reduction of partials ----------------
__global__ void k_reduce() {
    int e = blockIdx.x*256 + threadIdx.x;
    if (e < 4096) {
        float s = 0.f;
        for (int p = 0; p < 256; p++) s += g_Gpart[p*4096 + e];
        int tid = e >> 4, k = e & 15;
        int i = ((tid & 15) << 2) + (k >> 2);
        int j = ((tid >> 4) << 2) + (k & 3);
        g_G[i*64 + j] = s;
    } else if (e < 4160) {
        int c = e - 4096;
        float s = 0.f;
        for (int p = 0; p < 256; p++) s += g_spart[p*64 + c];
        g_s[c] = s;
    }
}

// ---------------- K2: analytic BN stats -> folded affine ----------------
__global__ void k_finalize(const float* __restrict__ W1, const float* __restrict__ b1,
                           const float* __restrict__ gamma, const float* __restrict__ beta) {
    int j = blockIdx.x;
    int d = threadIdx.x;
    float wdj = W1[d*HID + j];
    float q = 0.f;
#pragma unroll
    for (int c = 0; c < 64; c++) q += g_G[d*64 + c] * W1[c*HID + j];

    __shared__ float s1[64], s2[64];
    s1[d] = g_s[d]*wdj;   // -> s.w_j
    s2[d] = q*wdj;        // -> w_j^T G w_j
    __syncthreads();
    for (int off = 32; off > 0; off >>= 1) {
        if (d < off) { s1[d] += s1[d+off]; s2[d] += s2[d+off]; }
        __syncthreads();
    }
    if (d == 0) {
        const float invN = 1.f/(float)TOTA;
        float sw = s1[0], wGw = s2[0];
        float bj = b1[j];
        float m1 = sw*invN + bj;
        float m2 = (wGw + 2.f*bj*sw)*invN + bj*bj;
        float var = m2 - m1*m1;
        float A = rsqrtf(var + 1e-5f) * gamma[j];
        g_A[j] = A;
        g_B[j] = (bj - m1)*A + beta[j];
    }
}

// ---------------- K3: fused GEMM1 + BN + GELU + GEMM2 (32 rows / block) ----------------
// dynamic smem: W1sh[64][256] (16384) | zsh[32][68] (2176) | W2t[10][260] (2600)
__global__ void k_atoms(const float* __restrict__ z, const float* __restrict__ W1,
                        const float* __restrict__ W2, const float* __restrict__ b2,
                        float* __restrict__ out) {
    extern __shared__ float sm[];
    float* W1sh = sm;                    // 16384 floats
    float* zsh  = sm + 16384;            // 2176
    float* W2t  = sm + 16384 + 2176;     // 2600 (transposed W2, padded stride 260)
    int tid = threadIdx.x, b = blockIdx.x;
    const float* zp = z + b*(32*64);

    for (int idx = tid; idx < 16384; idx += 256) W1sh[idx] = W1[idx];
    for (int idx = tid; idx < 2048;  idx += 256) zsh[(idx>>6)*68 + (idx&63)] = zp[idx];
    for (int idx = tid; idx < 2560;  idx += 256) {
        int jj = idx / 10, kk = idx % 10;
        W2t[kk*260 + jj] = W2[idx];
    }
    __syncthreads();

    int lane = tid & 31, rq = tid >> 5;
    int r0 = rq << 2;                     // 8 row-quads of 4 rows
    float acc[4][8];
#pragma unroll
    for (int x = 0; x < 4; x++)
#pragma unroll
        for (int y = 0; y < 8; y++) acc[x][y] = 0.f;

    for (int c = 0; c < 64; c++) {
        float wv[8], zv[4];
#pragma unroll
        for (int y = 0; y < 8; y++) wv[y] = W1sh[(c<<8) + lane + (y<<5)];  // conflict-free: bank=lane
#pragma unroll
        for (int x = 0; x < 4; x++) zv[x] = zsh[(r0+x)*68 + c];            // warp-broadcast
#pragma unroll
        for (int x = 0; x < 4; x++)
#pragma unroll
            for (int y = 0; y < 8; y++)
                acc[x][y] += zv[x]*wv[y];
    }
    // folded BN + exact GELU
#pragma unroll
    for (int y = 0; y < 8; y++) {
        int j = lane + (y<<5);
        float A = g_A[j], B = g_B[j];
#pragma unroll
        for (int x = 0; x < 4; x++) {
            float t = acc[x][y]*A + B;
            acc[x][y] = 0.5f*t*(1.f + erff(t*0.70710678118654752f));
        }
    }
    __syncthreads();                      // everyone done with W1sh
    float* gsh = sm;                      // reuse as g[32][260]
#pragma unroll
    for (int x = 0; x < 4; x++)
#pragma unroll
        for (int y = 0; y < 8; y++)
            gsh[(r0+x)*260 + lane + (y<<5)] = acc[x][y];
    __syncthreads();

    // GEMM2: 32x10 outputs, float4 dots from smem
    for (int p = tid; p < 320; p += 256) {
        int r = p / 10, k = p % 10;
        const float4* gp4 = (const float4*)(gsh + r*260);
        const float4* wp4 = (const float4*)(W2t + k*260);
        float s = 0.f;
#pragma unroll
        for (int q = 0; q < 64; q++) {
            float4 a = gp4[q], w = wp4[q];
            s += a.x*w.x + a.y*w.y + a.z*w.z + a.w*w.w;
        }
        out[(b*32 + r)*10 + k] = s + b2[k];
    }
}

// ---------------- K4: per-molecule Y = Z Wf^T, logits, softmax ----------------
// dynamic smem: Wfsh[320][65] (20800) | zsh[32][68] (2176) | Ysh[320][33] (10560)
__global__ void k_edges(const float* __restrict__ z, float* __restrict__ out) {
    extern __shared__ float sm[];
    float* Wfsh = sm;                       // 20800 floats
    float* zsh  = sm + 20800;               // 2176
    float* Ysh  = sm + 20800 + 2176;        // 10560
    int tid = threadIdx.x, mol = blockIdx.x;
    const float* zp = z + mol*(32*64);

    for (int idx = tid; idx < 20480; idx += 256)
        Wfsh[(idx>>6)*65 + (idx&63)] = g_Wf[idx];
    for (int idx = tid; idx < 2048; idx += 256)
        zsh[(idx>>6)*68 + (idx&63)] = zp[idx];
    __syncthreads();

    // ---- Y phase: Y[td][a] = sum_c Wf[td][c] * z[a][c] ----
    // tile = (q, a0): td in {q, q+80, q+160, q+240} keeps lanes on distinct banks
    for (int tile = tid; tile < 320; tile += 256) {
        int q  = tile % 80;
        int a0 = (tile / 80) << 3;          // 0,8,16,24
        float acc[4][8];
#pragma unroll
        for (int y = 0; y < 4; y++)
#pragma unroll
            for (int x = 0; x < 8; x++) acc[y][x] = 0.f;

        for (int c = 0; c < 64; c++) {
            float wv[4], zv[8];
#pragma unroll
            for (int y = 0; y < 4; y++) wv[y] = Wfsh[(q + y*80)*65 + c];
#pragma unroll
            for (int x = 0; x < 8; x++) zv[x] = zsh[(a0+x)*68 + c];
#pragma unroll
            for (int y = 0; y < 4; y++)
#pragma unroll
                for (int x = 0; x < 8; x++)
                    acc[y][x] += wv[y]*zv[x];
        }
#pragma unroll
        for (int y = 0; y < 4; y++)
#pragma unroll
            for (int x = 0; x < 8; x++)
                Ysh[(q + y*80)*33 + a0 + x] = acc[y][x];
    }
    __syncthreads();

    // ---- edge phase: thread = (i-quad, j); holds all 5 types -> local softmax ----
    int j  = tid & 31;
    int i0 = (tid >> 5) << 2;
    float L[4][5];
#pragma unroll
    for (int x = 0; x < 4; x++)
#pragma unroll
        for (int t = 0; t < 5; t++) L[x][t] = 0.f;

    for (int d = 0; d < 64; d++) {
        float zv[4], yv[5];
#pragma unroll
        for (int x = 0; x < 4; x++) zv[x] = zsh[(i0+x)*68 + d];      // broadcast
#pragma unroll
        for (int t = 0; t < 5; t++) yv[t] = Ysh[(t*64 + d)*33 + j];  // bank = (td+j)%32, clean
#pragma unroll
        for (int x = 0; x < 4; x++)
#pragma unroll
            for (int t = 0; t < 5; t++)
                L[x][t] += zv[x]*yv[t];
    }

    float* eout = out + ATOM_OUT + mol*(NEDGE*5);
#pragma unroll
    for (int x = 0; x < 4; x++) {
        int i = i0 + x;
        if (i < j) {
            int e = 31*i - (i*(i-1))/2 + (j - i - 1);   // lexicographic combo index
            float m = L[x][0];
#pragma unroll
            for (int t = 1; t < 5; t++) m = fmaxf(m, L[x][t]);
            float ex[5], s = 0.f;
#pragma unroll
            for (int t = 0; t < 5; t++) { ex[t] = __expf(L[x][t] - m); s += ex[t]; }
            float inv = 1.f/s;
#pragma unroll
            for (int t = 0; t < 5; t++) eout[e*5 + t] = ex[t]*inv;
        }
    }
}

// ---------------- launch ----------------
extern "C" void kernel_launch(void* const* d_in, const int* in_sizes, int n_in,
                              void* d_out, int out_size) {
    const float* z  = (const float*)d_in[0];
    const float* W1 = (const float*)d_in[1];
    const float* b1 = (const float*)d_in[2];
    const float* gm = (const float*)d_in[3];
    const float* bt = (const float*)d_in[4];
    const float* W2 = (const float*)d_in[5];
    const float* b2 = (const float*)d_in[6];
    const float* bm = (const float*)d_in[7];
    float* out = (float*)d_out;
    (void)in_sizes; (void)n_in; (void)out_size;

    const int SMEM_ATOMS = (16384 + 2176 + 2600) * 4;          // 84640 B
    const int SMEM_EDGES = (20800 + 2176 + 10560) * 4;         // 134144 B
    cudaFuncSetAttribute(k_atoms, cudaFuncAttributeMaxDynamicSharedMemorySize, SMEM_ATOMS);
    cudaFuncSetAttribute(k_edges, cudaFuncAttributeMaxDynamicSharedMemorySize, SMEM_EDGES);

    k_prep    <<<80,   256>>>(bm);
    k_stats   <<<256,  256>>>(z);
    k_reduce  <<<17,   256>>>();
    k_finalize<<<256,  64 >>>(W1, b1, gm, bt);
    k_atoms   <<<1024, 256, SMEM_ATOMS>>>(z, W1, W2, b2, out);
    k_edges   <<<1024, 256, SMEM_EDGES>>>(z, out);
}